// round 1
// baseline (speedup 1.0000x reference)
#include <cuda_runtime.h>
#include <cstdint>

#define NNODES 10000
#define NEDGES 160000
#define HID    512
#define NOUT   16

// ---------------- device scratch (static: no allocation allowed) ----------------
__device__ float g_h[NNODES * HID];     // GEMM output (pre-aggregation)
__device__ float g_a[NNODES * HID];     // layer output (post agg+bias+relu)
__device__ float g_dinv[NNODES];
__device__ int   g_degcnt[NNODES];
__device__ int   g_fill[NNODES];
__device__ int   g_row[NNODES + 1];
__device__ int   g_srcv[NEDGES];
__device__ int   g_dstv[NEDGES];
__device__ int   g_adj[NEDGES];
__device__ int   g_is64;

// ---------------- edge dtype detection ----------------
// If edge_index is int64 (values < 2^31), every odd 32-bit word of the first E
// entries is zero. If int32, odd words are random node ids (P(all zero) ~ 1e-256).
__global__ void detect_kernel(const unsigned int* __restrict__ p) {
    int is64 = 1;
    for (int i = 1; i < 128; i += 2) {
        if (p[i] != 0u) { is64 = 0; break; }
    }
    g_is64 = is64;
}

__global__ void convert_kernel(const void* __restrict__ ei, int E) {
    int e = blockIdx.x * blockDim.x + threadIdx.x;
    if (e >= E) return;
    int s, d;
    if (g_is64) {
        const long long* p = (const long long*)ei;
        s = (int)p[e];
        d = (int)p[E + e];
    } else {
        const int* p = (const int*)ei;
        s = p[e];
        d = p[E + e];
    }
    g_srcv[e] = s;
    g_dstv[e] = d;
    atomicAdd(&g_degcnt[d], 1);
}

__global__ void dinv_kernel(int M) {
    int i = blockIdx.x * blockDim.x + threadIdx.x;
    if (i < M) g_dinv[i] = rsqrtf((float)g_degcnt[i] + 1.0f);
}

// single-block scan over node degrees -> CSR row offsets
__global__ void scan_kernel(int M) {
    __shared__ int part[1024];
    int t = threadIdx.x;
    int chunk = (M + 1023) / 1024;
    int b = t * chunk;
    int e = b + chunk; if (e > M) e = M;
    if (b > M) b = M;
    int s = 0;
    for (int i = b; i < e; i++) s += g_degcnt[i];
    part[t] = s;
    __syncthreads();
    // Hillis-Steele inclusive scan
    for (int off = 1; off < 1024; off <<= 1) {
        int v = (t >= off) ? part[t - off] : 0;
        __syncthreads();
        part[t] += v;
        __syncthreads();
    }
    int run = (t > 0) ? part[t - 1] : 0;
    for (int i = b; i < e; i++) {
        g_row[i] = run;
        run += g_degcnt[i];
    }
    if (e == M) g_row[M] = run;   // total (= E); benign multi-write of same value
}

__global__ void fill_kernel(int E) {
    int e = blockIdx.x * blockDim.x + threadIdx.x;
    if (e >= E) return;
    int d = g_dstv[e];
    int p = atomicAdd(&g_fill[d], 1);
    g_adj[g_row[d] + p] = g_srcv[e];
}

// ---------------- SGEMM: C[M,512] = A[M,512] @ B[512,512] (fp32) ----------------
// 128x128 block tile, BK=8, 256 threads, 8x8 per-thread register tile.
__global__ __launch_bounds__(256) void sgemm128(const float* __restrict__ A,
                                                const float* __restrict__ B,
                                                float* __restrict__ C, int M) {
    const int K = HID, Nc = HID;
    __shared__ float As[8][128];
    __shared__ float Bs[8][128];
    int bm = blockIdx.y * 128;
    int bn = blockIdx.x * 128;
    int tid = threadIdx.x;
    int tx = tid & 15, ty = tid >> 4;

    float acc[8][8];
#pragma unroll
    for (int i = 0; i < 8; i++)
#pragma unroll
        for (int j = 0; j < 8; j++) acc[i][j] = 0.0f;

    int arow = tid >> 1, acol = (tid & 1) * 4;   // A tile: 128x8, one float4/thread
    int brow = tid >> 5, bcol = (tid & 31) * 4;  // B tile: 8x128, one float4/thread

    for (int k0 = 0; k0 < K; k0 += 8) {
        float4 av;
        int gr = bm + arow;
        if (gr < M) av = *(const float4*)(A + (size_t)gr * K + k0 + acol);
        else        av = make_float4(0.f, 0.f, 0.f, 0.f);
        As[acol + 0][arow] = av.x;
        As[acol + 1][arow] = av.y;
        As[acol + 2][arow] = av.z;
        As[acol + 3][arow] = av.w;

        float4 bv = *(const float4*)(B + (size_t)(k0 + brow) * Nc + bn + bcol);
        *(float4*)&Bs[brow][bcol] = bv;
        __syncthreads();

#pragma unroll
        for (int k = 0; k < 8; k++) {
            float ra[8], rb[8];
            float4 a0 = *(const float4*)&As[k][ty * 8];
            float4 a1 = *(const float4*)&As[k][ty * 8 + 4];
            float4 b0 = *(const float4*)&Bs[k][tx * 8];
            float4 b1 = *(const float4*)&Bs[k][tx * 8 + 4];
            ra[0]=a0.x; ra[1]=a0.y; ra[2]=a0.z; ra[3]=a0.w;
            ra[4]=a1.x; ra[5]=a1.y; ra[6]=a1.z; ra[7]=a1.w;
            rb[0]=b0.x; rb[1]=b0.y; rb[2]=b0.z; rb[3]=b0.w;
            rb[4]=b1.x; rb[5]=b1.y; rb[6]=b1.z; rb[7]=b1.w;
#pragma unroll
            for (int i = 0; i < 8; i++)
#pragma unroll
                for (int j = 0; j < 8; j++) acc[i][j] += ra[i] * rb[j];
        }
        __syncthreads();
    }

#pragma unroll
    for (int i = 0; i < 8; i++) {
        int r = bm + ty * 8 + i;
        if (r < M) {
            float4 v0 = make_float4(acc[i][0], acc[i][1], acc[i][2], acc[i][3]);
            float4 v1 = make_float4(acc[i][4], acc[i][5], acc[i][6], acc[i][7]);
            *(float4*)(C + (size_t)r * Nc + bn + tx * 8)     = v0;
            *(float4*)(C + (size_t)r * Nc + bn + tx * 8 + 4) = v1;
        }
    }
}

// ---------------- aggregation: one block per node, fused self-loop+bias+relu ----
__global__ __launch_bounds__(128) void agg_kernel(const float* __restrict__ h,
                                                  const float* __restrict__ bias,
                                                  float* __restrict__ outp) {
    int v = blockIdx.x;
    int t = threadIdx.x;               // owns float4 at column t*4
    const float4* h4 = (const float4*)h;
    float dv = g_dinv[v];
    int beg = g_row[v], end = g_row[v + 1];

    float4 hv = h4[(size_t)v * (HID / 4) + t];
    float sl = dv * dv;
    float4 acc = make_float4(sl * hv.x, sl * hv.y, sl * hv.z, sl * hv.w);

    for (int j = beg; j < end; j++) {
        int s = g_adj[j];
        float nm = dv * g_dinv[s];
        float4 hs = h4[(size_t)s * (HID / 4) + t];
        acc.x += nm * hs.x;
        acc.y += nm * hs.y;
        acc.z += nm * hs.z;
        acc.w += nm * hs.w;
    }
    float4 bb = *(const float4*)(bias + t * 4);
    acc.x = fmaxf(acc.x + bb.x, 0.0f);
    acc.y = fmaxf(acc.y + bb.y, 0.0f);
    acc.z = fmaxf(acc.z + bb.z, 0.0f);
    acc.w = fmaxf(acc.w + bb.w, 0.0f);
    *(float4*)(outp + (size_t)v * HID + t * 4) = acc;
}

// ---------------- final logits: out[M,16] = h[M,512] @ Wl[512,16] + bl ---------
__global__ __launch_bounds__(256) void final_gemm(const float* __restrict__ h,
                                                  const float* __restrict__ Wl,
                                                  const float* __restrict__ bl,
                                                  float* __restrict__ out, int M) {
    __shared__ float Ws[HID][NOUT];
    int tx = threadIdx.x;  // 0..15  (output class)
    int ty = threadIdx.y;  // 0..15  (row within block)
    int tid = ty * 16 + tx;
    for (int i = tid; i < HID * NOUT; i += 256)
        Ws[i / NOUT][i % NOUT] = Wl[i];
    __syncthreads();

    int r = blockIdx.x * 16 + ty;
    if (r >= M) return;
    const float* hr = h + (size_t)r * HID;
    float acc = bl[tx];
#pragma unroll 8
    for (int k = 0; k < HID; k++)
        acc += hr[k] * Ws[k][tx];
    out[(size_t)r * NOUT + tx] = acc;
}

// ---------------- host launch ----------------
extern "C" void kernel_launch(void* const* d_in, const int* in_sizes, int n_in,
                              void* d_out, int out_size) {
    const float* x  = (const float*)d_in[0];
    const void*  ei = d_in[1];
    const float* W1 = (const float*)d_in[2];
    const float* b1 = (const float*)d_in[3];
    const float* W2 = (const float*)d_in[4];
    const float* b2 = (const float*)d_in[5];
    const float* Wl = (const float*)d_in[6];
    const float* bl = (const float*)d_in[7];
    float* out = (float*)d_out;

    int M = in_sizes[0] / HID;   // 10000
    int E = in_sizes[1] / 2;     // 160000 (element count identical for i32/i64)

    void *p_deg, *p_fill, *p_h, *p_a;
    cudaGetSymbolAddress(&p_deg, g_degcnt);
    cudaGetSymbolAddress(&p_fill, g_fill);
    cudaGetSymbolAddress(&p_h, g_h);
    cudaGetSymbolAddress(&p_a, g_a);
    float* hbuf = (float*)p_h;
    float* abuf = (float*)p_a;

    cudaMemsetAsync(p_deg, 0, sizeof(int) * NNODES);
    cudaMemsetAsync(p_fill, 0, sizeof(int) * NNODES);

    detect_kernel<<<1, 1>>>((const unsigned int*)ei);
    convert_kernel<<<(E + 255) / 256, 256>>>(ei, E);
    dinv_kernel<<<(M + 255) / 256, 256>>>(M);
    scan_kernel<<<1, 1024>>>(M);
    fill_kernel<<<(E + 255) / 256, 256>>>(E);

    dim3 gemm_grid(HID / 128, (M + 127) / 128);

    // layer 1
    sgemm128<<<gemm_grid, 256>>>(x, W1, hbuf, M);
    agg_kernel<<<M, 128>>>(hbuf, b1, abuf);
    // layer 2
    sgemm128<<<gemm_grid, 256>>>(abuf, W2, hbuf, M);
    agg_kernel<<<M, 128>>>(hbuf, b2, abuf);
    // logits
    final_gemm<<<(M + 15) / 16, dim3(16, 16)>>>(abuf, Wl, bl, out, M);
}

// round 3
// speedup vs baseline: 2.5618x; 2.5618x over previous
#include <cuda_runtime.h>
#include <cuda_bf16.h>
#include <cstdint>

#define NNODES 10000
#define NEDGES 160000
#define HID    512
#define NOUT   16
#define PB     ((NNODES + 255) / 256)   // scan partial blocks (40)

// ---------------- device scratch ----------------
__device__ float g_h[NNODES * HID];            // GEMM output fp32
__device__ float g_a[NNODES * HID];            // layer-2 agg output fp32
__device__ __nv_bfloat16 g_xh[NNODES * HID];   // x hi
__device__ __nv_bfloat16 g_xl[NNODES * HID];   // x lo
__device__ __nv_bfloat16 g_ah[NNODES * HID];   // agg1 out hi
__device__ __nv_bfloat16 g_al[NNODES * HID];   // agg1 out lo
__device__ __nv_bfloat16 g_w1h[HID * HID], g_w1l[HID * HID];  // W1^T hi/lo
__device__ __nv_bfloat16 g_w2h[HID * HID], g_w2l[HID * HID];  // W2^T hi/lo
__device__ float g_dinv[NNODES];
__device__ int   g_degcnt[NNODES];
__device__ int   g_fill[NNODES];
__device__ int   g_row[NNODES + 1];
__device__ int   g_srcv[NEDGES];
__device__ int   g_dstv[NEDGES];
__device__ int   g_adj[NEDGES];
__device__ int   g_part[PB];
__device__ int   g_ppref[PB];
__device__ int   g_is64;

__device__ __forceinline__ uint32_t smem_to_u32(const void* p) {
    uint32_t a;
    asm("{ .reg .u64 t; cvta.to.shared.u64 t, %1; cvt.u32.u64 %0, t; }" : "=r"(a) : "l"(p));
    return a;
}

// ---------------- setup kernels ----------------
__global__ void detect_kernel(const unsigned int* __restrict__ p) {
    int is64 = 1;
    for (int i = 1; i < 128; i += 2)
        if (p[i] != 0u) { is64 = 0; break; }
    g_is64 = is64;
}

__global__ void convert_kernel(const void* __restrict__ ei, int E) {
    int e = blockIdx.x * blockDim.x + threadIdx.x;
    if (e >= E) return;
    int s, d;
    if (g_is64) {
        const long long* p = (const long long*)ei;
        s = (int)p[e]; d = (int)p[E + e];
    } else {
        const int* p = (const int*)ei;
        s = p[e]; d = p[E + e];
    }
    g_srcv[e] = s; g_dstv[e] = d;
    atomicAdd(&g_degcnt[d], 1);
}

__global__ void dinv_kernel(int M) {
    int i = blockIdx.x * blockDim.x + threadIdx.x;
    if (i < M) g_dinv[i] = rsqrtf((float)g_degcnt[i] + 1.0f);
}

__global__ void part_kernel(int M) {
    __shared__ int sh[256];
    int i = blockIdx.x * 256 + threadIdx.x;
    sh[threadIdx.x] = (i < M) ? g_degcnt[i] : 0;
    __syncthreads();
    for (int o = 128; o > 0; o >>= 1) {
        if (threadIdx.x < o) sh[threadIdx.x] += sh[threadIdx.x + o];
        __syncthreads();
    }
    if (threadIdx.x == 0) g_part[blockIdx.x] = sh[0];
}

__global__ void partscan_kernel() {
    if (threadIdx.x == 0) {
        int run = 0;
        for (int b = 0; b < PB; b++) { int t = g_part[b]; g_ppref[b] = run; run += t; }
    }
}

__global__ void offsets_kernel(int M) {
    __shared__ int sh[256];
    int t = threadIdx.x;
    int i = blockIdx.x * 256 + t;
    int d = (i < M) ? g_degcnt[i] : 0;
    sh[t] = d;
    __syncthreads();
    for (int o = 1; o < 256; o <<= 1) {
        int v = (t >= o) ? sh[t - o] : 0;
        __syncthreads();
        sh[t] += v;
        __syncthreads();
    }
    int incl = sh[t];
    if (i < M) g_row[i] = g_ppref[blockIdx.x] + incl - d;
    if (i == M - 1) g_row[M] = g_ppref[blockIdx.x] + incl;
}

__global__ void fill_kernel(int E) {
    int e = blockIdx.x * blockDim.x + threadIdx.x;
    if (e >= E) return;
    int d = g_dstv[e];
    int p = atomicAdd(&g_fill[d], 1);
    g_adj[g_row[d] + p] = g_srcv[e];
}

// ---------------- fp32 -> bf16 hi/lo converts ----------------
__global__ void xconv_kernel(const float* __restrict__ x, int n4) {
    int i = blockIdx.x * blockDim.x + threadIdx.x;
    if (i >= n4) return;
    float4 v = ((const float4*)x)[i];
    __nv_bfloat16 h0 = __float2bfloat16(v.x), h1 = __float2bfloat16(v.y);
    __nv_bfloat16 h2 = __float2bfloat16(v.z), h3 = __float2bfloat16(v.w);
    __nv_bfloat16 l0 = __float2bfloat16(v.x - __bfloat162float(h0));
    __nv_bfloat16 l1 = __float2bfloat16(v.y - __bfloat162float(h1));
    __nv_bfloat16 l2 = __float2bfloat16(v.z - __bfloat162float(h2));
    __nv_bfloat16 l3 = __float2bfloat16(v.w - __bfloat162float(h3));
    ((__nv_bfloat162*)g_xh)[i * 2]     = __nv_bfloat162(h0, h1);
    ((__nv_bfloat162*)g_xh)[i * 2 + 1] = __nv_bfloat162(h2, h3);
    ((__nv_bfloat162*)g_xl)[i * 2]     = __nv_bfloat162(l0, l1);
    ((__nv_bfloat162*)g_xl)[i * 2 + 1] = __nv_bfloat162(l2, l3);
}

// transpose W [K,N] -> W^T [N,K], split hi/lo
__global__ void wconv_kernel(const float* __restrict__ W,
                             __nv_bfloat16* __restrict__ Th,
                             __nv_bfloat16* __restrict__ Tl) {
    __shared__ float tile[32][33];
    int n0 = blockIdx.x * 32, k0 = blockIdx.y * 32;
    int tx = threadIdx.x, ty = threadIdx.y;
#pragma unroll
    for (int j = 0; j < 32; j += 8)
        tile[ty + j][tx] = W[(size_t)(k0 + ty + j) * HID + n0 + tx];
    __syncthreads();
#pragma unroll
    for (int j = 0; j < 32; j += 8) {
        float v = tile[tx][ty + j];
        __nv_bfloat16 h = __float2bfloat16(v);
        __nv_bfloat16 l = __float2bfloat16(v - __bfloat162float(h));
        size_t o = (size_t)(n0 + ty + j) * HID + k0 + tx;
        Th[o] = h; Tl[o] = l;
    }
}

// ---------------- mma.sync split-bf16 GEMM: C[M,512] = A @ B^T ----------------
// A hi/lo [M,512] bf16 row-major; B hi/lo stored as B^T [N=512, K=512] K-major.
// Grid (4, ceil(M/128)), 256 threads = 8 warps; warp tile 32(M) x 64(N).
__global__ __launch_bounds__(256) void gemm_mma(const __nv_bfloat16* __restrict__ Ahg,
                                                const __nv_bfloat16* __restrict__ Alg,
                                                const __nv_bfloat16* __restrict__ Bhg,
                                                const __nv_bfloat16* __restrict__ Blg,
                                                float* __restrict__ C, int M) {
    __shared__ __nv_bfloat16 sAh[128][40];
    __shared__ __nv_bfloat16 sAl[128][40];
    __shared__ __nv_bfloat16 sBh[128][40];
    __shared__ __nv_bfloat16 sBl[128][40];

    int tid = threadIdx.x;
    int wid = tid >> 5, lane = tid & 31;
    int bm = blockIdx.y * 128, bn = blockIdx.x * 128;
    int wm = (wid >> 1) * 32;   // warp row base within tile
    int wn = (wid & 1) * 64;    // warp col base within tile

    float acc[2][8][4];
#pragma unroll
    for (int i = 0; i < 2; i++)
#pragma unroll
        for (int n = 0; n < 8; n++)
#pragma unroll
            for (int q = 0; q < 4; q++) acc[i][n][q] = 0.0f;

    // ldmatrix lane-address offsets
    int a_row = (lane & 7) + ((lane >> 3) & 1) * 8;
    int a_col = (lane >> 4) * 8;
    int b_row = (lane & 7) + (lane >> 4) * 8;
    int b_col = ((lane >> 3) & 1) * 8;

    const uint4* pAh = (const uint4*)Ahg;
    const uint4* pAl = (const uint4*)Alg;
    const uint4* pBh = (const uint4*)Bhg;
    const uint4* pBl = (const uint4*)Blg;
    uint4 zero4 = make_uint4(0, 0, 0, 0);

    for (int c = 0; c < HID / 32; c++) {
        // ---- load 4 tiles of 128x32 bf16 ----
#pragma unroll
        for (int h = 0; h < 2; h++) {
            int idx = tid + h * 256;       // 0..511
            int row = idx >> 2, q = idx & 3;
            size_t gA = (size_t)(bm + row) * (HID / 8) + c * 4 + q;
            size_t gB = (size_t)(bn + row) * (HID / 8) + c * 4 + q;
            bool va = (bm + row) < M;
            *(uint4*)&sAh[row][q * 8] = va ? pAh[gA] : zero4;
            *(uint4*)&sAl[row][q * 8] = va ? pAl[gA] : zero4;
            *(uint4*)&sBh[row][q * 8] = pBh[gB];
            *(uint4*)&sBl[row][q * 8] = pBl[gB];
        }
        __syncthreads();

        // ---- 3-term compute over this 32-wide K chunk ----
#pragma unroll
        for (int term = 0; term < 3; term++) {
            const __nv_bfloat16 (*sA)[40] = (term < 2) ? sAh : sAl;
            const __nv_bfloat16 (*sB)[40] = (term == 1) ? sBl : sBh;
#pragma unroll
            for (int ks = 0; ks < 2; ks++) {
                int k0 = ks * 16;
                uint32_t a[2][4];
#pragma unroll
                for (int i = 0; i < 2; i++) {
                    uint32_t addr = smem_to_u32(&sA[wm + i * 16 + a_row][k0 + a_col]);
                    asm volatile("ldmatrix.sync.aligned.m8n8.x4.shared.b16 {%0,%1,%2,%3}, [%4];"
                                 : "=r"(a[i][0]), "=r"(a[i][1]), "=r"(a[i][2]), "=r"(a[i][3])
                                 : "r"(addr));
                }
                uint32_t b[4][4];
#pragma unroll
                for (int j = 0; j < 4; j++) {
                    uint32_t addr = smem_to_u32(&sB[wn + j * 16 + b_row][k0 + b_col]);
                    asm volatile("ldmatrix.sync.aligned.m8n8.x4.shared.b16 {%0,%1,%2,%3}, [%4];"
                                 : "=r"(b[j][0]), "=r"(b[j][1]), "=r"(b[j][2]), "=r"(b[j][3])
                                 : "r"(addr));
                }
#pragma unroll
                for (int i = 0; i < 2; i++) {
#pragma unroll
                    for (int n = 0; n < 8; n++) {
                        uint32_t b0 = b[n >> 1][(n & 1) * 2];
                        uint32_t b1 = b[n >> 1][(n & 1) * 2 + 1];
                        asm volatile(
                            "mma.sync.aligned.m16n8k16.row.col.f32.bf16.bf16.f32 "
                            "{%0,%1,%2,%3}, {%4,%5,%6,%7}, {%8,%9}, {%0,%1,%2,%3};"
                            : "+f"(acc[i][n][0]), "+f"(acc[i][n][1]),
                              "+f"(acc[i][n][2]), "+f"(acc[i][n][3])
                            : "r"(a[i][0]), "r"(a[i][1]), "r"(a[i][2]), "r"(a[i][3]),
                              "r"(b0), "r"(b1));
                    }
                }
            }
        }
        __syncthreads();
    }

    // ---- epilogue ----
#pragma unroll
    for (int i = 0; i < 2; i++) {
#pragma unroll
        for (int n = 0; n < 8; n++) {
            int r0 = bm + wm + i * 16 + (lane >> 2);
            int col = bn + wn + n * 8 + (lane & 3) * 2;
            if (r0 < M)
                *(float2*)&C[(size_t)r0 * HID + col] = make_float2(acc[i][n][0], acc[i][n][1]);
            int r1 = r0 + 8;
            if (r1 < M)
                *(float2*)&C[(size_t)r1 * HID + col] = make_float2(acc[i][n][2], acc[i][n][3]);
        }
    }
}

// ---------------- aggregation (CSR gather) ----------------
__global__ __launch_bounds__(128) void agg_hl_kernel(const float* __restrict__ h,
                                                     const float* __restrict__ bias,
                                                     __nv_bfloat16* __restrict__ oh,
                                                     __nv_bfloat16* __restrict__ ol) {
    int v = blockIdx.x;
    int t = threadIdx.x;
    const float4* h4 = (const float4*)h;
    float dv = g_dinv[v];
    int beg = g_row[v], end = g_row[v + 1];

    float4 hv = h4[(size_t)v * (HID / 4) + t];
    float sl = dv * dv;
    float4 acc = make_float4(sl * hv.x, sl * hv.y, sl * hv.z, sl * hv.w);
    for (int j = beg; j < end; j++) {
        int s = g_adj[j];
        float nm = dv * g_dinv[s];
        float4 hs = h4[(size_t)s * (HID / 4) + t];
        acc.x += nm * hs.x; acc.y += nm * hs.y;
        acc.z += nm * hs.z; acc.w += nm * hs.w;
    }
    float4 bb = *(const float4*)(bias + t * 4);
    acc.x = fmaxf(acc.x + bb.x, 0.0f);
    acc.y = fmaxf(acc.y + bb.y, 0.0f);
    acc.z = fmaxf(acc.z + bb.z, 0.0f);
    acc.w = fmaxf(acc.w + bb.w, 0.0f);

    __nv_bfloat16 h0 = __float2bfloat16(acc.x), h1 = __float2bfloat16(acc.y);
    __nv_bfloat16 h2 = __float2bfloat16(acc.z), h3 = __float2bfloat16(acc.w);
    __nv_bfloat16 l0 = __float2bfloat16(acc.x - __bfloat162float(h0));
    __nv_bfloat16 l1 = __float2bfloat16(acc.y - __bfloat162float(h1));
    __nv_bfloat16 l2 = __float2bfloat16(acc.z - __bfloat162float(h2));
    __nv_bfloat16 l3 = __float2bfloat16(acc.w - __bfloat162float(h3));
    size_t o2 = (size_t)v * (HID / 2) + t * 2;
    ((__nv_bfloat162*)oh)[o2]     = __nv_bfloat162(h0, h1);
    ((__nv_bfloat162*)oh)[o2 + 1] = __nv_bfloat162(h2, h3);
    ((__nv_bfloat162*)ol)[o2]     = __nv_bfloat162(l0, l1);
    ((__nv_bfloat162*)ol)[o2 + 1] = __nv_bfloat162(l2, l3);
}

__global__ __launch_bounds__(128) void agg_f32_kernel(const float* __restrict__ h,
                                                      const float* __restrict__ bias,
                                                      float* __restrict__ outp) {
    int v = blockIdx.x;
    int t = threadIdx.x;
    const float4* h4 = (const float4*)h;
    float dv = g_dinv[v];
    int beg = g_row[v], end = g_row[v + 1];

    float4 hv = h4[(size_t)v * (HID / 4) + t];
    float sl = dv * dv;
    float4 acc = make_float4(sl * hv.x, sl * hv.y, sl * hv.z, sl * hv.w);
    for (int j = beg; j < end; j++) {
        int s = g_adj[j];
        float nm = dv * g_dinv[s];
        float4 hs = h4[(size_t)s * (HID / 4) + t];
        acc.x += nm * hs.x; acc.y += nm * hs.y;
        acc.z += nm * hs.z; acc.w += nm * hs.w;
    }
    float4 bb = *(const float4*)(bias + t * 4);
    acc.x = fmaxf(acc.x + bb.x, 0.0f);
    acc.y = fmaxf(acc.y + bb.y, 0.0f);
    acc.z = fmaxf(acc.z + bb.z, 0.0f);
    acc.w = fmaxf(acc.w + bb.w, 0.0f);
    *(float4*)(outp + (size_t)v * HID + t * 4) = acc;
}

// ---------------- final logits ----------------
__global__ __launch_bounds__(256) void final_gemm(const float* __restrict__ h,
                                                  const float* __restrict__ Wl,
                                                  const float* __restrict__ bl,
                                                  float* __restrict__ out, int M) {
    __shared__ float Ws[HID][NOUT];
    int tx = threadIdx.x;
    int ty = threadIdx.y;
    int tid = ty * 16 + tx;
    for (int i = tid; i < HID * NOUT; i += 256)
        Ws[i / NOUT][i % NOUT] = Wl[i];
    __syncthreads();

    int r = blockIdx.x * 16 + ty;
    if (r >= M) return;
    const float* hr = h + (size_t)r * HID;
    float acc = bl[tx];
#pragma unroll 8
    for (int k = 0; k < HID; k++)
        acc += hr[k] * Ws[k][tx];
    out[(size_t)r * NOUT + tx] = acc;
}

// ---------------- host launch ----------------
extern "C" void kernel_launch(void* const* d_in, const int* in_sizes, int n_in,
                              void* d_out, int out_size) {
    const float* x  = (const float*)d_in[0];
    const void*  ei = d_in[1];
    const float* W1 = (const float*)d_in[2];
    const float* b1 = (const float*)d_in[3];
    const float* W2 = (const float*)d_in[4];
    const float* b2 = (const float*)d_in[5];
    const float* Wl = (const float*)d_in[6];
    const float* bl = (const float*)d_in[7];
    float* out = (float*)d_out;

    int M = in_sizes[0] / HID;
    int E = in_sizes[1] / 2;

    void *p_deg, *p_fill, *p_h, *p_a, *p_xh, *p_xl, *p_ah, *p_al;
    void *p_w1h, *p_w1l, *p_w2h, *p_w2l;
    cudaGetSymbolAddress(&p_deg, g_degcnt);
    cudaGetSymbolAddress(&p_fill, g_fill);
    cudaGetSymbolAddress(&p_h, g_h);
    cudaGetSymbolAddress(&p_a, g_a);
    cudaGetSymbolAddress(&p_xh, g_xh);
    cudaGetSymbolAddress(&p_xl, g_xl);
    cudaGetSymbolAddress(&p_ah, g_ah);
    cudaGetSymbolAddress(&p_al, g_al);
    cudaGetSymbolAddress(&p_w1h, g_w1h);
    cudaGetSymbolAddress(&p_w1l, g_w1l);
    cudaGetSymbolAddress(&p_w2h, g_w2h);
    cudaGetSymbolAddress(&p_w2l, g_w2l);

    cudaMemsetAsync(p_deg, 0, sizeof(int) * NNODES);
    cudaMemsetAsync(p_fill, 0, sizeof(int) * NNODES);

    // graph preprocessing
    detect_kernel<<<1, 1>>>((const unsigned int*)ei);
    convert_kernel<<<(E + 255) / 256, 256>>>(ei, E);
    dinv_kernel<<<(M + 255) / 256, 256>>>(M);
    part_kernel<<<PB, 256>>>(M);
    partscan_kernel<<<1, 32>>>();
    offsets_kernel<<<PB, 256>>>(M);
    fill_kernel<<<(E + 255) / 256, 256>>>(E);

    // precision-split conversions
    int n4 = M * HID / 4;
    xconv_kernel<<<(n4 + 255) / 256, 256>>>(x, n4);
    wconv_kernel<<<dim3(16, 16), dim3(32, 8)>>>(W1, (__nv_bfloat16*)p_w1h, (__nv_bfloat16*)p_w1l);
    wconv_kernel<<<dim3(16, 16), dim3(32, 8)>>>(W2, (__nv_bfloat16*)p_w2h, (__nv_bfloat16*)p_w2l);

    dim3 ggrid(HID / 128, (M + 127) / 128);

    // layer 1
    gemm_mma<<<ggrid, 256>>>((const __nv_bfloat16*)p_xh, (const __nv_bfloat16*)p_xl,
                             (const __nv_bfloat16*)p_w1h, (const __nv_bfloat16*)p_w1l,
                             (float*)p_h, M);
    agg_hl_kernel<<<M, 128>>>((const float*)p_h, b1,
                              (__nv_bfloat16*)p_ah, (__nv_bfloat16*)p_al);
    // layer 2
    gemm_mma<<<ggrid, 256>>>((const __nv_bfloat16*)p_ah, (const __nv_bfloat16*)p_al,
                             (const __nv_bfloat16*)p_w2h, (const __nv_bfloat16*)p_w2l,
                             (float*)p_h, M);
    agg_f32_kernel<<<M, 128>>>((const float*)p_h, b2, (float*)p_a);
    // logits
    final_gemm<<<(M + 15) / 16, dim3(16, 16)>>>((const float*)p_a, Wl, bl, out, M);
}

// round 5
// speedup vs baseline: 2.6325x; 1.0276x over previous
#include <cuda_runtime.h>
#include <cuda_bf16.h>
#include <cstdint>

#define NNODES 10000
#define NEDGES 160000
#define HID    512
#define NOUT   16
#define PB     ((NNODES + 255) / 256)   // scan partial blocks (40)

// ---------------- device scratch ----------------
__device__ float g_h[NNODES * HID];            // GEMM output fp32
__device__ float g_a[NNODES * HID];            // layer-2 agg output fp32
__device__ __nv_bfloat16 g_xh[NNODES * HID];   // x hi
__device__ __nv_bfloat16 g_xl[NNODES * HID];   // x lo
__device__ __nv_bfloat16 g_ah[NNODES * HID];   // agg1 out hi
__device__ __nv_bfloat16 g_al[NNODES * HID];   // agg1 out lo
__device__ __nv_bfloat16 g_w1h[HID * HID], g_w1l[HID * HID];  // W1^T hi/lo
__device__ __nv_bfloat16 g_w2h[HID * HID], g_w2l[HID * HID];  // W2^T hi/lo
__device__ float g_dinv[NNODES];
__device__ int   g_degcnt[NNODES];
__device__ int   g_fill[NNODES];
__device__ int   g_row[NNODES + 1];
__device__ int   g_srcv[NEDGES];
__device__ int   g_dstv[NEDGES];
__device__ int   g_adj[NEDGES];
__device__ int   g_part[PB];
__device__ int   g_ppref[PB];
__device__ int   g_is64;

__device__ __forceinline__ uint32_t smem_to_u32(const void* p) {
    uint32_t a;
    asm("{ .reg .u64 t; cvta.to.shared.u64 t, %1; cvt.u32.u64 %0, t; }" : "=r"(a) : "l"(p));
    return a;
}

__device__ __forceinline__ void cp_async16(uint32_t dst, const void* src, bool pred) {
    int sz = pred ? 16 : 0;
    asm volatile("cp.async.cg.shared.global [%0], [%1], 16, %2;\n"
                 :: "r"(dst), "l"(src), "r"(sz));
}
__device__ __forceinline__ void cp_commit() {
    asm volatile("cp.async.commit_group;\n" ::: "memory");
}
template <int N>
__device__ __forceinline__ void cp_wait() {
    asm volatile("cp.async.wait_group %0;\n" :: "n"(N) : "memory");
}

__device__ __forceinline__ void ldsm4(uint32_t addr, uint32_t r[4]) {
    asm volatile("ldmatrix.sync.aligned.m8n8.x4.shared.b16 {%0,%1,%2,%3}, [%4];"
                 : "=r"(r[0]), "=r"(r[1]), "=r"(r[2]), "=r"(r[3]) : "r"(addr));
}

// ---------------- setup kernels ----------------
__global__ void detect_kernel(const unsigned int* __restrict__ p) {
    int is64 = 1;
    for (int i = 1; i < 128; i += 2)
        if (p[i] != 0u) { is64 = 0; break; }
    g_is64 = is64;
}

__global__ void convert_kernel(const void* __restrict__ ei, int E) {
    int e = blockIdx.x * blockDim.x + threadIdx.x;
    if (e >= E) return;
    int s, d;
    if (g_is64) {
        const long long* p = (const long long*)ei;
        s = (int)p[e]; d = (int)p[E + e];
    } else {
        const int* p = (const int*)ei;
        s = p[e]; d = p[E + e];
    }
    g_srcv[e] = s; g_dstv[e] = d;
    atomicAdd(&g_degcnt[d], 1);
}

// per-256 partial sums of degree + dinv computation (fused)
__global__ void part_kernel(int M) {
    __shared__ int sh[256];
    int i = blockIdx.x * 256 + threadIdx.x;
    int d = (i < M) ? g_degcnt[i] : 0;
    if (i < M) g_dinv[i] = rsqrtf((float)d + 1.0f);
    sh[threadIdx.x] = d;
    __syncthreads();
    for (int o = 128; o > 0; o >>= 1) {
        if (threadIdx.x < o) sh[threadIdx.x] += sh[threadIdx.x + o];
        __syncthreads();
    }
    if (threadIdx.x == 0) g_part[blockIdx.x] = sh[0];
}

__global__ void partscan_kernel() {
    if (threadIdx.x == 0) {
        int run = 0;
        for (int b = 0; b < PB; b++) { int t = g_part[b]; g_ppref[b] = run; run += t; }
    }
}

__global__ void offsets_kernel(int M) {
    __shared__ int sh[256];
    int t = threadIdx.x;
    int i = blockIdx.x * 256 + t;
    int d = (i < M) ? g_degcnt[i] : 0;
    sh[t] = d;
    __syncthreads();
    for (int o = 1; o < 256; o <<= 1) {
        int v = (t >= o) ? sh[t - o] : 0;
        __syncthreads();
        sh[t] += v;
        __syncthreads();
    }
    int incl = sh[t];
    if (i < M) g_row[i] = g_ppref[blockIdx.x] + incl - d;
    if (i == M - 1) g_row[M] = g_ppref[blockIdx.x] + incl;
}

__global__ void fill_kernel(int E) {
    int e = blockIdx.x * blockDim.x + threadIdx.x;
    if (e >= E) return;
    int d = g_dstv[e];
    int p = atomicAdd(&g_fill[d], 1);
    g_adj[g_row[d] + p] = g_srcv[e];
}

// ---------------- fp32 -> bf16 hi/lo converts ----------------
__global__ void xconv_kernel(const float* __restrict__ x, int n4) {
    int i = blockIdx.x * blockDim.x + threadIdx.x;
    if (i >= n4) return;
    float4 v = ((const float4*)x)[i];
    __nv_bfloat16 h0 = __float2bfloat16(v.x), h1 = __float2bfloat16(v.y);
    __nv_bfloat16 h2 = __float2bfloat16(v.z), h3 = __float2bfloat16(v.w);
    __nv_bfloat16 l0 = __float2bfloat16(v.x - __bfloat162float(h0));
    __nv_bfloat16 l1 = __float2bfloat16(v.y - __bfloat162float(h1));
    __nv_bfloat16 l2 = __float2bfloat16(v.z - __bfloat162float(h2));
    __nv_bfloat16 l3 = __float2bfloat16(v.w - __bfloat162float(h3));
    ((__nv_bfloat162*)g_xh)[i * 2]     = __nv_bfloat162(h0, h1);
    ((__nv_bfloat162*)g_xh)[i * 2 + 1] = __nv_bfloat162(h2, h3);
    ((__nv_bfloat162*)g_xl)[i * 2]     = __nv_bfloat162(l0, l1);
    ((__nv_bfloat162*)g_xl)[i * 2 + 1] = __nv_bfloat162(l2, l3);
}

// transpose W [K,N] -> W^T [N,K], split hi/lo
__global__ void wconv_kernel(const float* __restrict__ W,
                             __nv_bfloat16* __restrict__ Th,
                             __nv_bfloat16* __restrict__ Tl) {
    __shared__ float tile[32][33];
    int n0 = blockIdx.x * 32, k0 = blockIdx.y * 32;
    int tx = threadIdx.x, ty = threadIdx.y;
#pragma unroll
    for (int j = 0; j < 32; j += 8)
        tile[ty + j][tx] = W[(size_t)(k0 + ty + j) * HID + n0 + tx];
    __syncthreads();
#pragma unroll
    for (int j = 0; j < 32; j += 8) {
        float v = tile[tx][ty + j];
        __nv_bfloat16 h = __float2bfloat16(v);
        __nv_bfloat16 l = __float2bfloat16(v - __bfloat162float(h));
        size_t o = (size_t)(n0 + ty + j) * HID + k0 + tx;
        Th[o] = h; Tl[o] = l;
    }
}

// ---------------- pipelined mma.sync split-bf16 GEMM ----------------
// C[M,512] = A @ B^T. Grid (4, ceil(M/128)), 256 threads = 8 warps.
// Warp tile 32(M) x 64(N). cp.async 2-stage pipeline over 16 k-chunks of 32.
#define TSTRIDE 40                    // padded row stride (bf16 elems)
#define TILEB   (128 * TSTRIDE * 2)   // bytes per 128x32 tile (10240)
#define STAGEB  (4 * TILEB)           // 4 tiles per stage (Ah,Al,Bh,Bl)

__global__ __launch_bounds__(256) void gemm_mma(const __nv_bfloat16* __restrict__ Ahg,
                                                const __nv_bfloat16* __restrict__ Alg,
                                                const __nv_bfloat16* __restrict__ Bhg,
                                                const __nv_bfloat16* __restrict__ Blg,
                                                float* __restrict__ C, int M) {
    extern __shared__ char dynsm[];
    uint32_t sbase = smem_to_u32(dynsm);

    int tid = threadIdx.x;
    int wid = tid >> 5, lane = tid & 31;
    int bm = blockIdx.y * 128, bn = blockIdx.x * 128;
    int wm = (wid >> 1) * 32;
    int wn = (wid & 1) * 64;

    float acc[2][8][4];
#pragma unroll
    for (int i = 0; i < 2; i++)
#pragma unroll
        for (int n = 0; n < 8; n++)
#pragma unroll
            for (int q = 0; q < 4; q++) acc[i][n][q] = 0.0f;

    // ldmatrix lane addressing
    int a_row = (lane & 7) + ((lane >> 3) & 1) * 8;
    int a_col = (lane >> 4) * 8;
    int b_row = (lane & 7) + (lane >> 4) * 8;
    int b_col = ((lane >> 3) & 1) * 8;

    // per-thread copy slot: tid -> row 0..127, two 16B quads (q0, q0+1)
    int row0 = tid >> 1, q0 = (tid & 1) * 2;

    const __nv_bfloat16* gAh = Ahg;
    const __nv_bfloat16* gAl = Alg;
    const __nv_bfloat16* gBh = Bhg;
    const __nv_bfloat16* gBl = Blg;
    bool avalid = (bm + row0) < M;

    auto issue = [&](int c, int s) {
        uint32_t st = sbase + s * STAGEB;
        size_t gA = (size_t)(bm + row0) * HID + c * 32;
        size_t gB = (size_t)(bn + row0) * HID + c * 32;
        uint32_t soff = (uint32_t)(row0 * TSTRIDE) * 2;
#pragma unroll
        for (int q = 0; q < 2; q++) {
            uint32_t dq = soff + (q0 + q) * 16;
            cp_async16(st + dq, gAh + gA + (q0 + q) * 8, avalid);
            cp_async16(st + TILEB + dq, gAl + gA + (q0 + q) * 8, avalid);
            cp_async16(st + 2 * TILEB + dq, gBh + gB + (q0 + q) * 8, true);
            cp_async16(st + 3 * TILEB + dq, gBl + gB + (q0 + q) * 8, true);
        }
        cp_commit();
    };

    issue(0, 0);

    for (int c = 0; c < HID / 32; c++) {
        int s = c & 1;
        if (c + 1 < HID / 32) {
            issue(c + 1, s ^ 1);
            cp_wait<1>();
        } else {
            cp_wait<0>();
        }
        __syncthreads();

        uint32_t st = sbase + s * STAGEB;
        uint32_t bAh = st, bAl = st + TILEB, bBh = st + 2 * TILEB, bBl = st + 3 * TILEB;

#pragma unroll
        for (int ks = 0; ks < 2; ks++) {
            int k0 = ks * 16;
            uint32_t ah[2][4], al[2][4], bh[4][4], bl[4][4];
#pragma unroll
            for (int i = 0; i < 2; i++) {
                uint32_t off = ((uint32_t)(wm + i * 16 + a_row) * TSTRIDE + k0 + a_col) * 2;
                ldsm4(bAh + off, ah[i]);
                ldsm4(bAl + off, al[i]);
            }
#pragma unroll
            for (int j = 0; j < 4; j++) {
                uint32_t off = ((uint32_t)(wn + j * 16 + b_row) * TSTRIDE + k0 + b_col) * 2;
                ldsm4(bBh + off, bh[j]);
                ldsm4(bBl + off, bl[j]);
            }

#pragma unroll
            for (int i = 0; i < 2; i++) {
#pragma unroll
                for (int n = 0; n < 8; n++) {
                    uint32_t h0 = bh[n >> 1][(n & 1) * 2];
                    uint32_t h1 = bh[n >> 1][(n & 1) * 2 + 1];
                    asm volatile(
                        "mma.sync.aligned.m16n8k16.row.col.f32.bf16.bf16.f32 "
                        "{%0,%1,%2,%3}, {%4,%5,%6,%7}, {%8,%9}, {%0,%1,%2,%3};"
                        : "+f"(acc[i][n][0]), "+f"(acc[i][n][1]),
                          "+f"(acc[i][n][2]), "+f"(acc[i][n][3])
                        : "r"(ah[i][0]), "r"(ah[i][1]), "r"(ah[i][2]), "r"(ah[i][3]),
                          "r"(h0), "r"(h1));
                    uint32_t l0 = bl[n >> 1][(n & 1) * 2];
                    uint32_t l1 = bl[n >> 1][(n & 1) * 2 + 1];
                    asm volatile(
                        "mma.sync.aligned.m16n8k16.row.col.f32.bf16.bf16.f32 "
                        "{%0,%1,%2,%3}, {%4,%5,%6,%7}, {%8,%9}, {%0,%1,%2,%3};"
                        : "+f"(acc[i][n][0]), "+f"(acc[i][n][1]),
                          "+f"(acc[i][n][2]), "+f"(acc[i][n][3])
                        : "r"(ah[i][0]), "r"(ah[i][1]), "r"(ah[i][2]), "r"(ah[i][3]),
                          "r"(l0), "r"(l1));
                    asm volatile(
                        "mma.sync.aligned.m16n8k16.row.col.f32.bf16.bf16.f32 "
                        "{%0,%1,%2,%3}, {%4,%5,%6,%7}, {%8,%9}, {%0,%1,%2,%3};"
                        : "+f"(acc[i][n][0]), "+f"(acc[i][n][1]),
                          "+f"(acc[i][n][2]), "+f"(acc[i][n][3])
                        : "r"(al[i][0]), "r"(al[i][1]), "r"(al[i][2]), "r"(al[i][3]),
                          "r"(h0), "r"(h1));
                }
            }
        }
        __syncthreads();
    }

    // ---- epilogue ----
#pragma unroll
    for (int i = 0; i < 2; i++) {
#pragma unroll
        for (int n = 0; n < 8; n++) {
            int r0 = bm + wm + i * 16 + (lane >> 2);
            int col = bn + wn + n * 8 + (lane & 3) * 2;
            if (r0 < M)
                *(float2*)&C[(size_t)r0 * HID + col] = make_float2(acc[i][n][0], acc[i][n][1]);
            int r1 = r0 + 8;
            if (r1 < M)
                *(float2*)&C[(size_t)r1 * HID + col] = make_float2(acc[i][n][2], acc[i][n][3]);
        }
    }
}

// ---------------- aggregation (CSR gather) ----------------
__global__ __launch_bounds__(128) void agg_hl_kernel(const float* __restrict__ h,
                                                     const float* __restrict__ bias,
                                                     __nv_bfloat16* __restrict__ oh,
                                                     __nv_bfloat16* __restrict__ ol) {
    int v = blockIdx.x;
    int t = threadIdx.x;
    const float4* h4 = (const float4*)h;
    float dv = g_dinv[v];
    int beg = g_row[v], end = g_row[v + 1];

    float4 hv = h4[(size_t)v * (HID / 4) + t];
    float sl = dv * dv;
    float4 acc = make_float4(sl * hv.x, sl * hv.y, sl * hv.z, sl * hv.w);
    for (int j = beg; j < end; j++) {
        int s = g_adj[j];
        float nm = dv * g_dinv[s];
        float4 hs = h4[(size_t)s * (HID / 4) + t];
        acc.x += nm * hs.x; acc.y += nm * hs.y;
        acc.z += nm * hs.z; acc.w += nm * hs.w;
    }
    float4 bb = *(const float4*)(bias + t * 4);
    acc.x = fmaxf(acc.x + bb.x, 0.0f);
    acc.y = fmaxf(acc.y + bb.y, 0.0f);
    acc.z = fmaxf(acc.z + bb.z, 0.0f);
    acc.w = fmaxf(acc.w + bb.w, 0.0f);

    __nv_bfloat16 h0 = __float2bfloat16(acc.x), h1 = __float2bfloat16(acc.y);
    __nv_bfloat16 h2 = __float2bfloat16(acc.z), h3 = __float2bfloat16(acc.w);
    __nv_bfloat16 l0 = __float2bfloat16(acc.x - __bfloat162float(h0));
    __nv_bfloat16 l1 = __float2bfloat16(acc.y - __bfloat162float(h1));
    __nv_bfloat16 l2 = __float2bfloat16(acc.z - __bfloat162float(h2));
    __nv_bfloat16 l3 = __float2bfloat16(acc.w - __bfloat162float(h3));
    size_t o2 = (size_t)v * (HID / 2) + t * 2;
    ((__nv_bfloat162*)oh)[o2]     = __nv_bfloat162(h0, h1);
    ((__nv_bfloat162*)oh)[o2 + 1] = __nv_bfloat162(h2, h3);
    ((__nv_bfloat162*)ol)[o2]     = __nv_bfloat162(l0, l1);
    ((__nv_bfloat162*)ol)[o2 + 1] = __nv_bfloat162(l2, l3);
}

__global__ __launch_bounds__(128) void agg_f32_kernel(const float* __restrict__ h,
                                                      const float* __restrict__ bias,
                                                      float* __restrict__ outp) {
    int v = blockIdx.x;
    int t = threadIdx.x;
    const float4* h4 = (const float4*)h;
    float dv = g_dinv[v];
    int beg = g_row[v], end = g_row[v + 1];

    float4 hv = h4[(size_t)v * (HID / 4) + t];
    float sl = dv * dv;
    float4 acc = make_float4(sl * hv.x, sl * hv.y, sl * hv.z, sl * hv.w);
    for (int j = beg; j < end; j++) {
        int s = g_adj[j];
        float nm = dv * g_dinv[s];
        float4 hs = h4[(size_t)s * (HID / 4) + t];
        acc.x += nm * hs.x; acc.y += nm * hs.y;
        acc.z += nm * hs.z; acc.w += nm * hs.w;
    }
    float4 bb = *(const float4*)(bias + t * 4);
    acc.x = fmaxf(acc.x + bb.x, 0.0f);
    acc.y = fmaxf(acc.y + bb.y, 0.0f);
    acc.z = fmaxf(acc.z + bb.z, 0.0f);
    acc.w = fmaxf(acc.w + bb.w, 0.0f);
    *(float4*)(outp + (size_t)v * HID + t * 4) = acc;
}

// ---------------- final logits ----------------
__global__ __launch_bounds__(256) void final_gemm(const float* __restrict__ h,
                                                  const float* __restrict__ Wl,
                                                  const float* __restrict__ bl,
                                                  float* __restrict__ out, int M) {
    __shared__ float Ws[HID][NOUT];
    int tx = threadIdx.x;
    int ty = threadIdx.y;
    int tid = ty * 16 + tx;
    for (int i = tid; i < HID * NOUT; i += 256)
        Ws[i / NOUT][i % NOUT] = Wl[i];
    __syncthreads();

    int r = blockIdx.x * 16 + ty;
    if (r >= M) return;
    const float* hr = h + (size_t)r * HID;
    float acc = bl[tx];
#pragma unroll 8
    for (int k = 0; k < HID; k++)
        acc += hr[k] * Ws[k][tx];
    out[(size_t)r * NOUT + tx] = acc;
}

// ---------------- host launch ----------------
extern "C" void kernel_launch(void* const* d_in, const int* in_sizes, int n_in,
                              void* d_out, int out_size) {
    const float* x  = (const float*)d_in[0];
    const void*  ei = d_in[1];
    const float* W1 = (const float*)d_in[2];
    const float* b1 = (const float*)d_in[3];
    const float* W2 = (const float*)d_in[4];
    const float* b2 = (const float*)d_in[5];
    const float* Wl = (const float*)d_in[6];
    const float* bl = (const float*)d_in[7];
    float* out = (float*)d_out;

    int M = in_sizes[0] / HID;
    int E = in_sizes[1] / 2;

    void *p_deg, *p_fill, *p_h, *p_a, *p_xh, *p_xl, *p_ah, *p_al;
    void *p_w1h, *p_w1l, *p_w2h, *p_w2l;
    cudaGetSymbolAddress(&p_deg, g_degcnt);
    cudaGetSymbolAddress(&p_fill, g_fill);
    cudaGetSymbolAddress(&p_h, g_h);
    cudaGetSymbolAddress(&p_a, g_a);
    cudaGetSymbolAddress(&p_xh, g_xh);
    cudaGetSymbolAddress(&p_xl, g_xl);
    cudaGetSymbolAddress(&p_ah, g_ah);
    cudaGetSymbolAddress(&p_al, g_al);
    cudaGetSymbolAddress(&p_w1h, g_w1h);
    cudaGetSymbolAddress(&p_w1l, g_w1l);
    cudaGetSymbolAddress(&p_w2h, g_w2h);
    cudaGetSymbolAddress(&p_w2l, g_w2l);

    const int GEMM_SMEM = 2 * STAGEB;   // 81920 bytes
    cudaFuncSetAttribute(gemm_mma, cudaFuncAttributeMaxDynamicSharedMemorySize, GEMM_SMEM);

    cudaMemsetAsync(p_deg, 0, sizeof(int) * NNODES);
    cudaMemsetAsync(p_fill, 0, sizeof(int) * NNODES);

    // graph preprocessing
    detect_kernel<<<1, 1>>>((const unsigned int*)ei);
    convert_kernel<<<(E + 255) / 256, 256>>>(ei, E);
    part_kernel<<<PB, 256>>>(M);
    partscan_kernel<<<1, 32>>>();
    offsets_kernel<<<PB, 256>>>(M);
    fill_kernel<<<(E + 255) / 256, 256>>>(E);

    // precision-split conversions
    int n4 = M * HID / 4;
    xconv_kernel<<<(n4 + 255) / 256, 256>>>(x, n4);
    wconv_kernel<<<dim3(16, 16), dim3(32, 8)>>>(W1, (__nv_bfloat16*)p_w1h, (__nv_bfloat16*)p_w1l);
    wconv_kernel<<<dim3(16, 16), dim3(32, 8)>>>(W2, (__nv_bfloat16*)p_w2h, (__nv_bfloat16*)p_w2l);

    dim3 ggrid(HID / 128, (M + 127) / 128);

    // layer 1
    gemm_mma<<<ggrid, 256, GEMM_SMEM>>>((const __nv_bfloat16*)p_xh, (const __nv_bfloat16*)p_xl,
                                        (const __nv_bfloat16*)p_w1h, (const __nv_bfloat16*)p_w1l,
                                        (float*)p_h, M);
    agg_hl_kernel<<<M, 128>>>((const float*)p_h, b1,
                              (__nv_bfloat16*)p_ah, (__nv_bfloat16*)p_al);
    // layer 2
    gemm_mma<<<ggrid, 256, GEMM_SMEM>>>((const __nv_bfloat16*)p_ah, (const __nv_bfloat16*)p_al,
                                        (const __nv_bfloat16*)p_w2h, (const __nv_bfloat16*)p_w2l,
                                        (float*)p_h, M);
    agg_f32_kernel<<<M, 128>>>((const float*)p_h, b2, (float*)p_a);
    // logits
    final_gemm<<<(M + 15) / 16, dim3(16, 16)>>>((const float*)p_a, Wl, bl, out, M);
}

// round 6
// speedup vs baseline: 2.7692x; 1.0519x over previous
#include <cuda_runtime.h>
#include <cuda_bf16.h>
#include <cstdint>

#define NNODES 10000
#define NEDGES 160000
#define HID    512
#define NOUT   16

// ---------------- device scratch ----------------
__device__ float g_h[NNODES * HID];            // GEMM output fp32
__device__ float g_a[NNODES * HID];            // layer-2 agg output fp32
__device__ __nv_bfloat16 g_xh[NNODES * HID];   // x hi
__device__ __nv_bfloat16 g_xl[NNODES * HID];   // x lo
__device__ __nv_bfloat16 g_ah[NNODES * HID];   // agg1 out hi
__device__ __nv_bfloat16 g_al[NNODES * HID];   // agg1 out lo
__device__ __nv_bfloat16 g_w1h[HID * HID], g_w1l[HID * HID];  // W1^T hi/lo
__device__ __nv_bfloat16 g_w2h[HID * HID], g_w2l[HID * HID];  // W2^T hi/lo
__device__ float g_dinv[NNODES];
__device__ int   g_degcnt[NNODES];
__device__ int   g_fill[NNODES];
__device__ int   g_rowstart[NNODES];
__device__ int   g_total;
__device__ int   g_srcv[NEDGES];
__device__ int   g_dsttmp[NEDGES];
__device__ int   g_adjout[NEDGES];

__device__ __forceinline__ uint32_t smem_to_u32(const void* p) {
    uint32_t a;
    asm("{ .reg .u64 t; cvta.to.shared.u64 t, %1; cvt.u32.u64 %0, t; }" : "=r"(a) : "l"(p));
    return a;
}

__device__ __forceinline__ void cp_async16(uint32_t dst, const void* src, bool pred) {
    int sz = pred ? 16 : 0;
    asm volatile("cp.async.cg.shared.global [%0], [%1], 16, %2;\n"
                 :: "r"(dst), "l"(src), "r"(sz));
}
__device__ __forceinline__ void cp_commit() {
    asm volatile("cp.async.commit_group;\n" ::: "memory");
}
template <int N>
__device__ __forceinline__ void cp_wait() {
    asm volatile("cp.async.wait_group %0;\n" :: "n"(N) : "memory");
}

__device__ __forceinline__ void ldsm4(uint32_t addr, uint32_t r[4]) {
    asm volatile("ldmatrix.sync.aligned.m8n8.x4.shared.b16 {%0,%1,%2,%3}, [%4];"
                 : "=r"(r[0]), "=r"(r[1]), "=r"(r[2]), "=r"(r[3]) : "r"(addr));
}

// ---------------- launch 0: x hi/lo split + zero counters ----------------
__global__ void xconv_kernel(const float* __restrict__ x, int n4) {
    int i = blockIdx.x * blockDim.x + threadIdx.x;
    if (i < NNODES) { g_degcnt[i] = 0; g_fill[i] = 0; }
    if (i == 0) g_total = 0;
    if (i >= n4) return;
    float4 v = ((const float4*)x)[i];
    __nv_bfloat16 h0 = __float2bfloat16(v.x), h1 = __float2bfloat16(v.y);
    __nv_bfloat16 h2 = __float2bfloat16(v.z), h3 = __float2bfloat16(v.w);
    __nv_bfloat16 l0 = __float2bfloat16(v.x - __bfloat162float(h0));
    __nv_bfloat16 l1 = __float2bfloat16(v.y - __bfloat162float(h1));
    __nv_bfloat16 l2 = __float2bfloat16(v.z - __bfloat162float(h2));
    __nv_bfloat16 l3 = __float2bfloat16(v.w - __bfloat162float(h3));
    ((__nv_bfloat162*)g_xh)[i * 2]     = __nv_bfloat162(h0, h1);
    ((__nv_bfloat162*)g_xh)[i * 2 + 1] = __nv_bfloat162(h2, h3);
    ((__nv_bfloat162*)g_xl)[i * 2]     = __nv_bfloat162(l0, l1);
    ((__nv_bfloat162*)g_xl)[i * 2 + 1] = __nv_bfloat162(l2, l3);
}

// ---------------- launch 1: both weight transposes + hi/lo split ----------------
__global__ void wconv_kernel(const float* __restrict__ W1,
                             const float* __restrict__ W2) {
    __shared__ float tile[32][33];
    const float* W = blockIdx.z ? W2 : W1;
    __nv_bfloat16* Th = blockIdx.z ? g_w2h : g_w1h;
    __nv_bfloat16* Tl = blockIdx.z ? g_w2l : g_w1l;
    int n0 = blockIdx.x * 32, k0 = blockIdx.y * 32;
    int tx = threadIdx.x, ty = threadIdx.y;
#pragma unroll
    for (int j = 0; j < 32; j += 8)
        tile[ty + j][tx] = W[(size_t)(k0 + ty + j) * HID + n0 + tx];
    __syncthreads();
#pragma unroll
    for (int j = 0; j < 32; j += 8) {
        float v = tile[tx][ty + j];
        __nv_bfloat16 h = __float2bfloat16(v);
        __nv_bfloat16 l = __float2bfloat16(v - __bfloat162float(h));
        size_t o = (size_t)(n0 + ty + j) * HID + k0 + tx;
        Th[o] = h; Tl[o] = l;
    }
}

// ---------------- launch 2: edge convert + degree count (detect inlined) ----------------
__global__ void convert_kernel(const void* __restrict__ ei, int E) {
    __shared__ int s_is64;
    if (threadIdx.x == 0) {
        const unsigned int* p = (const unsigned int*)ei;
        int is64 = 1;
        for (int i = 1; i < 128; i += 2)
            if (p[i] != 0u) { is64 = 0; break; }
        s_is64 = is64;
    }
    __syncthreads();
    int e = blockIdx.x * blockDim.x + threadIdx.x;
    if (e >= E) return;
    int s, d;
    if (s_is64) {
        const long long* p = (const long long*)ei;
        s = (int)p[e]; d = (int)p[E + e];
    } else {
        const int* p = (const int*)ei;
        s = p[e]; d = p[E + e];
    }
    g_srcv[e] = s;
    g_dsttmp[e] = d;
    atomicAdd(&g_degcnt[d], 1);
}

// ---------------- launch 3: row starts (unordered CSR) + dinv ----------------
__global__ void rowstart_kernel(int M) {
    int i = blockIdx.x * blockDim.x + threadIdx.x;
    if (i >= M) return;
    int d = g_degcnt[i];
    g_dinv[i] = rsqrtf((float)d + 1.0f);
    g_rowstart[i] = atomicAdd(&g_total, d);
}

// ---------------- launch 4: adjacency fill ----------------
__global__ void fill_kernel(int E) {
    int e = blockIdx.x * blockDim.x + threadIdx.x;
    if (e >= E) return;
    int d = g_dsttmp[e];
    int s = g_srcv[e];
    int p = atomicAdd(&g_fill[d], 1);
    g_adjout[g_rowstart[d] + p] = s;
}

// ---------------- pipelined mma.sync split-bf16 GEMM ----------------
#define TSTRIDE 40
#define TILEB   (128 * TSTRIDE * 2)
#define STAGEB  (4 * TILEB)

__global__ __launch_bounds__(256) void gemm_mma(const __nv_bfloat16* __restrict__ Ahg,
                                                const __nv_bfloat16* __restrict__ Alg,
                                                const __nv_bfloat16* __restrict__ Bhg,
                                                const __nv_bfloat16* __restrict__ Blg,
                                                float* __restrict__ C, int M) {
    extern __shared__ char dynsm[];
    uint32_t sbase = smem_to_u32(dynsm);

    int tid = threadIdx.x;
    int wid = tid >> 5, lane = tid & 31;
    int bm = blockIdx.y * 128, bn = blockIdx.x * 128;
    int wm = (wid >> 1) * 32;
    int wn = (wid & 1) * 64;

    float acc[2][8][4];
#pragma unroll
    for (int i = 0; i < 2; i++)
#pragma unroll
        for (int n = 0; n < 8; n++)
#pragma unroll
            for (int q = 0; q < 4; q++) acc[i][n][q] = 0.0f;

    int a_row = (lane & 7) + ((lane >> 3) & 1) * 8;
    int a_col = (lane >> 4) * 8;
    int b_row = (lane & 7) + (lane >> 4) * 8;
    int b_col = ((lane >> 3) & 1) * 8;

    int row0 = tid >> 1, q0 = (tid & 1) * 2;
    bool avalid = (bm + row0) < M;

    auto issue = [&](int c, int s) {
        uint32_t st = sbase + s * STAGEB;
        size_t gA = (size_t)(bm + row0) * HID + c * 32;
        size_t gB = (size_t)(bn + row0) * HID + c * 32;
        uint32_t soff = (uint32_t)(row0 * TSTRIDE) * 2;
#pragma unroll
        for (int q = 0; q < 2; q++) {
            uint32_t dq = soff + (q0 + q) * 16;
            cp_async16(st + dq, Ahg + gA + (q0 + q) * 8, avalid);
            cp_async16(st + TILEB + dq, Alg + gA + (q0 + q) * 8, avalid);
            cp_async16(st + 2 * TILEB + dq, Bhg + gB + (q0 + q) * 8, true);
            cp_async16(st + 3 * TILEB + dq, Blg + gB + (q0 + q) * 8, true);
        }
        cp_commit();
    };

    issue(0, 0);

    for (int c = 0; c < HID / 32; c++) {
        int s = c & 1;
        if (c + 1 < HID / 32) {
            issue(c + 1, s ^ 1);
            cp_wait<1>();
        } else {
            cp_wait<0>();
        }
        __syncthreads();

        uint32_t st = sbase + s * STAGEB;
        uint32_t bAh = st, bAl = st + TILEB, bBh = st + 2 * TILEB, bBl = st + 3 * TILEB;

#pragma unroll
        for (int ks = 0; ks < 2; ks++) {
            int k0 = ks * 16;
            uint32_t ah[2][4], al[2][4], bh[4][4], bl[4][4];
#pragma unroll
            for (int i = 0; i < 2; i++) {
                uint32_t off = ((uint32_t)(wm + i * 16 + a_row) * TSTRIDE + k0 + a_col) * 2;
                ldsm4(bAh + off, ah[i]);
                ldsm4(bAl + off, al[i]);
            }
#pragma unroll
            for (int j = 0; j < 4; j++) {
                uint32_t off = ((uint32_t)(wn + j * 16 + b_row) * TSTRIDE + k0 + b_col) * 2;
                ldsm4(bBh + off, bh[j]);
                ldsm4(bBl + off, bl[j]);
            }

#pragma unroll
            for (int i = 0; i < 2; i++) {
#pragma unroll
                for (int n = 0; n < 8; n++) {
                    uint32_t h0 = bh[n >> 1][(n & 1) * 2];
                    uint32_t h1 = bh[n >> 1][(n & 1) * 2 + 1];
                    asm volatile(
                        "mma.sync.aligned.m16n8k16.row.col.f32.bf16.bf16.f32 "
                        "{%0,%1,%2,%3}, {%4,%5,%6,%7}, {%8,%9}, {%0,%1,%2,%3};"
                        : "+f"(acc[i][n][0]), "+f"(acc[i][n][1]),
                          "+f"(acc[i][n][2]), "+f"(acc[i][n][3])
                        : "r"(ah[i][0]), "r"(ah[i][1]), "r"(ah[i][2]), "r"(ah[i][3]),
                          "r"(h0), "r"(h1));
                    uint32_t l0 = bl[n >> 1][(n & 1) * 2];
                    uint32_t l1 = bl[n >> 1][(n & 1) * 2 + 1];
                    asm volatile(
                        "mma.sync.aligned.m16n8k16.row.col.f32.bf16.bf16.f32 "
                        "{%0,%1,%2,%3}, {%4,%5,%6,%7}, {%8,%9}, {%0,%1,%2,%3};"
                        : "+f"(acc[i][n][0]), "+f"(acc[i][n][1]),
                          "+f"(acc[i][n][2]), "+f"(acc[i][n][3])
                        : "r"(ah[i][0]), "r"(ah[i][1]), "r"(ah[i][2]), "r"(ah[i][3]),
                          "r"(l0), "r"(l1));
                    asm volatile(
                        "mma.sync.aligned.m16n8k16.row.col.f32.bf16.bf16.f32 "
                        "{%0,%1,%2,%3}, {%4,%5,%6,%7}, {%8,%9}, {%0,%1,%2,%3};"
                        : "+f"(acc[i][n][0]), "+f"(acc[i][n][1]),
                          "+f"(acc[i][n][2]), "+f"(acc[i][n][3])
                        : "r"(al[i][0]), "r"(al[i][1]), "r"(al[i][2]), "r"(al[i][3]),
                          "r"(h0), "r"(h1));
                }
            }
        }
        __syncthreads();
    }

#pragma unroll
    for (int i = 0; i < 2; i++) {
#pragma unroll
        for (int n = 0; n < 8; n++) {
            int r0 = bm + wm + i * 16 + (lane >> 2);
            int col = bn + wn + n * 8 + (lane & 3) * 2;
            if (r0 < M)
                *(float2*)&C[(size_t)r0 * HID + col] = make_float2(acc[i][n][0], acc[i][n][1]);
            int r1 = r0 + 8;
            if (r1 < M)
                *(float2*)&C[(size_t)r1 * HID + col] = make_float2(acc[i][n][2], acc[i][n][3]);
        }
    }
}

// ---------------- aggregation (unordered CSR gather) ----------------
__global__ __launch_bounds__(128) void agg_hl_kernel(const float* __restrict__ h,
                                                     const float* __restrict__ bias,
                                                     __nv_bfloat16* __restrict__ oh,
                                                     __nv_bfloat16* __restrict__ ol) {
    int v = blockIdx.x;
    int t = threadIdx.x;
    const float4* h4 = (const float4*)h;
    float dv = g_dinv[v];
    int beg = g_rowstart[v], end = beg + g_degcnt[v];

    float4 hv = h4[(size_t)v * (HID / 4) + t];
    float sl = dv * dv;
    float4 acc = make_float4(sl * hv.x, sl * hv.y, sl * hv.z, sl * hv.w);
    for (int j = beg; j < end; j++) {
        int s = g_adjout[j];
        float nm = dv * g_dinv[s];
        float4 hs = h4[(size_t)s * (HID / 4) + t];
        acc.x += nm * hs.x; acc.y += nm * hs.y;
        acc.z += nm * hs.z; acc.w += nm * hs.w;
    }
    float4 bb = *(const float4*)(bias + t * 4);
    acc.x = fmaxf(acc.x + bb.x, 0.0f);
    acc.y = fmaxf(acc.y + bb.y, 0.0f);
    acc.z = fmaxf(acc.z + bb.z, 0.0f);
    acc.w = fmaxf(acc.w + bb.w, 0.0f);

    __nv_bfloat16 h0 = __float2bfloat16(acc.x), h1 = __float2bfloat16(acc.y);
    __nv_bfloat16 h2 = __float2bfloat16(acc.z), h3 = __float2bfloat16(acc.w);
    __nv_bfloat16 l0 = __float2bfloat16(acc.x - __bfloat162float(h0));
    __nv_bfloat16 l1 = __float2bfloat16(acc.y - __bfloat162float(h1));
    __nv_bfloat16 l2 = __float2bfloat16(acc.z - __bfloat162float(h2));
    __nv_bfloat16 l3 = __float2bfloat16(acc.w - __bfloat162float(h3));
    size_t o2 = (size_t)v * (HID / 2) + t * 2;
    ((__nv_bfloat162*)oh)[o2]     = __nv_bfloat162(h0, h1);
    ((__nv_bfloat162*)oh)[o2 + 1] = __nv_bfloat162(h2, h3);
    ((__nv_bfloat162*)ol)[o2]     = __nv_bfloat162(l0, l1);
    ((__nv_bfloat162*)ol)[o2 + 1] = __nv_bfloat162(l2, l3);
}

__global__ __launch_bounds__(128) void agg_f32_kernel(const float* __restrict__ h,
                                                      const float* __restrict__ bias,
                                                      float* __restrict__ outp) {
    int v = blockIdx.x;
    int t = threadIdx.x;
    const float4* h4 = (const float4*)h;
    float dv = g_dinv[v];
    int beg = g_rowstart[v], end = beg + g_degcnt[v];

    float4 hv = h4[(size_t)v * (HID / 4) + t];
    float sl = dv * dv;
    float4 acc = make_float4(sl * hv.x, sl * hv.y, sl * hv.z, sl * hv.w);
    for (int j = beg; j < end; j++) {
        int s = g_adjout[j];
        float nm = dv * g_dinv[s];
        float4 hs = h4[(size_t)s * (HID / 4) + t];
        acc.x += nm * hs.x; acc.y += nm * hs.y;
        acc.z += nm * hs.z; acc.w += nm * hs.w;
    }
    float4 bb = *(const float4*)(bias + t * 4);
    acc.x = fmaxf(acc.x + bb.x, 0.0f);
    acc.y = fmaxf(acc.y + bb.y, 0.0f);
    acc.z = fmaxf(acc.z + bb.z, 0.0f);
    acc.w = fmaxf(acc.w + bb.w, 0.0f);
    *(float4*)(outp + (size_t)v * HID + t * 4) = acc;
}

// ---------------- final logits ----------------
__global__ __launch_bounds__(256) void final_gemm(const float* __restrict__ h,
                                                  const float* __restrict__ Wl,
                                                  const float* __restrict__ bl,
                                                  float* __restrict__ out, int M) {
    __shared__ float Ws[HID][NOUT];
    int tx = threadIdx.x;
    int ty = threadIdx.y;
    int tid = ty * 16 + tx;
    for (int i = tid; i < HID * NOUT; i += 256)
        Ws[i / NOUT][i % NOUT] = Wl[i];
    __syncthreads();

    int r = blockIdx.x * 16 + ty;
    if (r >= M) return;
    const float* hr = h + (size_t)r * HID;
    float acc = bl[tx];
#pragma unroll 8
    for (int k = 0; k < HID; k++)
        acc += hr[k] * Ws[k][tx];
    out[(size_t)r * NOUT + tx] = acc;
}

// ---------------- host launch ----------------
extern "C" void kernel_launch(void* const* d_in, const int* in_sizes, int n_in,
                              void* d_out, int out_size) {
    const float* x  = (const float*)d_in[0];
    const void*  ei = d_in[1];
    const float* W1 = (const float*)d_in[2];
    const float* b1 = (const float*)d_in[3];
    const float* W2 = (const float*)d_in[4];
    const float* b2 = (const float*)d_in[5];
    const float* Wl = (const float*)d_in[6];
    const float* bl = (const float*)d_in[7];
    float* out = (float*)d_out;

    int M = in_sizes[0] / HID;
    int E = in_sizes[1] / 2;

    void *p_h, *p_a, *p_xh, *p_xl, *p_ah, *p_al;
    void *p_w1h, *p_w1l, *p_w2h, *p_w2l;
    cudaGetSymbolAddress(&p_h, g_h);
    cudaGetSymbolAddress(&p_a, g_a);
    cudaGetSymbolAddress(&p_xh, g_xh);
    cudaGetSymbolAddress(&p_xl, g_xl);
    cudaGetSymbolAddress(&p_ah, g_ah);
    cudaGetSymbolAddress(&p_al, g_al);
    cudaGetSymbolAddress(&p_w1h, g_w1h);
    cudaGetSymbolAddress(&p_w1l, g_w1l);
    cudaGetSymbolAddress(&p_w2h, g_w2h);
    cudaGetSymbolAddress(&p_w2l, g_w2l);

    const int GEMM_SMEM = 2 * STAGEB;   // 81920 bytes
    cudaFuncSetAttribute(gemm_mma, cudaFuncAttributeMaxDynamicSharedMemorySize, GEMM_SMEM);

    int n4 = M * HID / 4;

    // launch 0: x split + zero counters
    xconv_kernel<<<(n4 + 255) / 256, 256>>>(x, n4);
    // launch 1: both weight transposes
    wconv_kernel<<<dim3(16, 16, 2), dim3(32, 8)>>>(W1, W2);
    // launch 2: edge convert + degrees (detect inlined)
    convert_kernel<<<(E + 255) / 256, 256>>>(ei, E);
    // launch 3: row starts + dinv
    rowstart_kernel<<<(M + 255) / 256, 256>>>(M);
    // launch 4: adjacency fill
    fill_kernel<<<(E + 255) / 256, 256>>>(E);

    dim3 ggrid(HID / 128, (M + 127) / 128);

    // launch 5: layer-1 GEMM  <-- ncu -s 5 captures this
    gemm_mma<<<ggrid, 256, GEMM_SMEM>>>((const __nv_bfloat16*)p_xh, (const __nv_bfloat16*)p_xl,
                                        (const __nv_bfloat16*)p_w1h, (const __nv_bfloat16*)p_w1l,
                                        (float*)p_h, M);
    agg_hl_kernel<<<M, 128>>>((const float*)p_h, b1,
                              (__nv_bfloat16*)p_ah, (__nv_bfloat16*)p_al);
    gemm_mma<<<ggrid, 256, GEMM_SMEM>>>((const __nv_bfloat16*)p_ah, (const __nv_bfloat16*)p_al,
                                        (const __nv_bfloat16*)p_w2h, (const __nv_bfloat16*)p_w2l,
                                        (float*)p_h, M);
    agg_f32_kernel<<<M, 128>>>((const float*)p_h, b2, (float*)p_a);
    final_gemm<<<(M + 15) / 16, dim3(16, 16)>>>((const float*)p_a, Wl, bl, out, M);
}